// round 3
// baseline (speedup 1.0000x reference)
#include <cuda_runtime.h>
#include <cuda_bf16.h>
#include <cstdint>
#include <cstddef>

// Pairwise Euclidean distance, B=8192, K=256, D=3072, fp32.
// out[b,k] = sqrt(max(||x||^2 + ||c||^2 - 2 x.c, eps))
// sm_100 base ISA only (no tcgen05/TMA): warp-specialized bf16 mma.sync GEMM,
// 8-stage mbarrier ring, producers convert fp32->bf16 and accumulate norms.

#define BB 8192
#define KK 256
#define DD 3072
#define BM 128
#define BN 128
#define BK 32
#define NT (DD / BK)            // 96 k-tiles
#define NSTAGE 8
#define NTHREADS 512            // warps 0-7 compute, 8-15 produce
#define EPS_F 1e-12f

#define LDS_STRIDE 40           // bf16 elems per row (80B), conflict-free frags
#define ATILE_B (BM * LDS_STRIDE * 2)        // 10240 B
#define STAGE_B (2 * ATILE_B)                // 20480 B (A then B)
#define OFF_BAR  (NSTAGE * STAGE_B)          // 163840: 16B/stage (full,empty)
#define OFF_XSQ  (OFF_BAR + 512)
#define OFF_CSQ  (OFF_XSQ + 512)
#define SMEM_BYTES (OFF_CSQ + 512)

static __device__ __forceinline__ uint32_t s2u(const void* p) {
    uint32_t a;
    asm("{.reg .u64 t; cvta.to.shared.u64 t, %1; cvt.u32.u64 %0, t;}"
        : "=r"(a) : "l"(p));
    return a;
}

static __device__ __forceinline__ void mbar_init(uint32_t mbar, uint32_t cnt) {
    asm volatile("mbarrier.init.shared.b64 [%0], %1;" :: "r"(mbar), "r"(cnt) : "memory");
}

static __device__ __forceinline__ void mbar_arrive(uint32_t mbar) {
    asm volatile("mbarrier.arrive.release.cta.shared::cta.b64 _, [%0];"
                 :: "r"(mbar) : "memory");
}

static __device__ __forceinline__ void mbar_wait(uint32_t mbar, uint32_t parity) {
    asm volatile(
        "{\n\t"
        ".reg .pred P1;\n\t"
        "LAB_WAIT_%=:\n\t"
        "mbarrier.try_wait.parity.acquire.cta.shared::cta.b64 P1, [%0], %1, 0x989680;\n\t"
        "@P1 bra.uni LAB_DONE_%=;\n\t"
        "bra.uni LAB_WAIT_%=;\n\t"
        "LAB_DONE_%=:\n\t"
        "}"
        :: "r"(mbar), "r"(parity) : "memory");
}

static __device__ __forceinline__ uint2 cvt2x4(float4 a, float4 b) {
    __nv_bfloat162 p0 = __float22bfloat162_rn(make_float2(a.x, a.y));
    __nv_bfloat162 p1 = __float22bfloat162_rn(make_float2(a.z, a.w));
    __nv_bfloat162 p2 = __float22bfloat162_rn(make_float2(b.x, b.y));
    __nv_bfloat162 p3 = __float22bfloat162_rn(make_float2(b.z, b.w));
    uint2 u;
    u.x = (*reinterpret_cast<uint32_t*>(&p0)) |
          ((uint32_t)*reinterpret_cast<uint16_t*>(&p1) << 16);
    // repack carefully: p0 holds (a.x,a.y) as 2 bf16 in 32 bits already
    u.x = *reinterpret_cast<uint32_t*>(&p0);
    u.y = *reinterpret_cast<uint32_t*>(&p1);
    (void)p2; (void)p3;
    return u;
}

__global__ void __launch_bounds__(NTHREADS, 1)
rbf_ws_kernel(const float* __restrict__ X, const float* __restrict__ C,
              float* __restrict__ out)
{
    extern __shared__ __align__(16) char smem[];
    const uint32_t sb = s2u(smem);
    const int tid  = threadIdx.x;
    const int wid  = tid >> 5;
    const int lane = tid & 31;
    const int bm = blockIdx.y;
    const int bn = blockIdx.x;

    if (tid < 128) {
        ((float*)(smem + OFF_XSQ))[tid] = 0.f;
        ((float*)(smem + OFF_CSQ))[tid] = 0.f;
    }
    if (tid == 0) {
        #pragma unroll
        for (int s = 0; s < NSTAGE; s++) {
            mbar_init(sb + OFF_BAR + s * 16, 256);     // full: 256 producer threads
            mbar_init(sb + OFF_BAR + s * 16 + 8, 8);   // empty: 8 compute warps
        }
    }
    __syncthreads();

    if (wid >= 8) {
        // ================= PRODUCER: 256 threads =================
        // thread -> (row 0..127, half 0..1); per stage 4+4 LDG.128, cvt, 2+2 STS.128
        const int pid  = tid - 256;
        const int row  = pid & 127;
        const int half = pid >> 7;
        const float* gA = X + (size_t)(bm * BM + row) * DD + half * 16;
        const float* gB = C + (size_t)(bn * BN + row) * DD + half * 16;
        // dest: byte offset of (row, col half*16) in tile
        const uint32_t drow = (uint32_t)row * (LDS_STRIDE * 2) + (uint32_t)half * 32;

        float4 ra[2][4], rb[2][4];
        float xs = 0.f, cs = 0.f;

        auto ldg_stage = [&](int kt, int buf) {
            const float4* sA = reinterpret_cast<const float4*>(gA + kt * BK);
            const float4* sB = reinterpret_cast<const float4*>(gB + kt * BK);
            #pragma unroll
            for (int c = 0; c < 4; c++) { ra[buf][c] = sA[c]; rb[buf][c] = sB[c]; }
        };

        ldg_stage(0, 0);
        ldg_stage(1, 1);

        #pragma unroll 1
        for (int kt = 0; kt < NT; kt++) {
            const int s = kt % NSTAGE;
            const int buf = kt & 1;
            if (kt >= NSTAGE)
                mbar_wait(sb + OFF_BAR + s * 16 + 8, ((kt / NSTAGE) - 1) & 1);

            const uint32_t dA = sb + (uint32_t)s * STAGE_B + drow;
            const uint32_t dB = dA + ATILE_B;
            #pragma unroll
            for (int c = 0; c < 2; c++) {
                float4 v0 = ra[buf][2 * c], v1 = ra[buf][2 * c + 1];
                xs += v0.x * v0.x + v0.y * v0.y + v0.z * v0.z + v0.w * v0.w
                    + v1.x * v1.x + v1.y * v1.y + v1.z * v1.z + v1.w * v1.w;
                __nv_bfloat162 p0 = __float22bfloat162_rn(make_float2(v0.x, v0.y));
                __nv_bfloat162 p1 = __float22bfloat162_rn(make_float2(v0.z, v0.w));
                __nv_bfloat162 p2 = __float22bfloat162_rn(make_float2(v1.x, v1.y));
                __nv_bfloat162 p3 = __float22bfloat162_rn(make_float2(v1.z, v1.w));
                uint4 u;
                u.x = *reinterpret_cast<uint32_t*>(&p0);
                u.y = *reinterpret_cast<uint32_t*>(&p1);
                u.z = *reinterpret_cast<uint32_t*>(&p2);
                u.w = *reinterpret_cast<uint32_t*>(&p3);
                asm volatile("st.shared.v4.b32 [%0], {%1,%2,%3,%4};"
                             :: "r"(dA + c * 16), "r"(u.x), "r"(u.y), "r"(u.z), "r"(u.w)
                             : "memory");

                v0 = rb[buf][2 * c]; v1 = rb[buf][2 * c + 1];
                cs += v0.x * v0.x + v0.y * v0.y + v0.z * v0.z + v0.w * v0.w
                    + v1.x * v1.x + v1.y * v1.y + v1.z * v1.z + v1.w * v1.w;
                p0 = __float22bfloat162_rn(make_float2(v0.x, v0.y));
                p1 = __float22bfloat162_rn(make_float2(v0.z, v0.w));
                p2 = __float22bfloat162_rn(make_float2(v1.x, v1.y));
                p3 = __float22bfloat162_rn(make_float2(v1.z, v1.w));
                u.x = *reinterpret_cast<uint32_t*>(&p0);
                u.y = *reinterpret_cast<uint32_t*>(&p1);
                u.z = *reinterpret_cast<uint32_t*>(&p2);
                u.w = *reinterpret_cast<uint32_t*>(&p3);
                asm volatile("st.shared.v4.b32 [%0], {%1,%2,%3,%4};"
                             :: "r"(dB + c * 16), "r"(u.x), "r"(u.y), "r"(u.z), "r"(u.w)
                             : "memory");
            }
            mbar_arrive(sb + OFF_BAR + s * 16);
            if (kt + 2 < NT) ldg_stage(kt + 2, buf);
        }
        atomicAdd(&((float*)(smem + OFF_XSQ))[row], xs);
        atomicAdd(&((float*)(smem + OFF_CSQ))[row], cs);
    } else {
        // ================= COMPUTE: 8 warps, warp tile 32x64 =================
        const int wm = wid & 3;
        const int wn = wid >> 2;
        const int fr = lane >> 2;
        const int fc = (lane & 3) * 2;

        float acc[2][8][4];
        #pragma unroll
        for (int i = 0; i < 2; i++)
            #pragma unroll
            for (int j = 0; j < 8; j++)
                #pragma unroll
                for (int q = 0; q < 4; q++) acc[i][j][q] = 0.f;

        #pragma unroll 1
        for (int kt = 0; kt < NT; kt++) {
            const int s = kt % NSTAGE;
            mbar_wait(sb + OFF_BAR + s * 16, (kt / NSTAGE) & 1);
            const char* As = smem + s * STAGE_B;
            const char* Bs = As + ATILE_B;

            #pragma unroll
            for (int ks = 0; ks < 2; ks++) {
                const int kof = ks * 16;
                uint32_t bfrag[8][2];
                #pragma unroll
                for (int j = 0; j < 8; j++) {
                    const char* bp = Bs + (wn * 64 + j * 8 + fr) * (LDS_STRIDE * 2)
                                        + (kof + fc) * 2;
                    bfrag[j][0] = *reinterpret_cast<const uint32_t*>(bp);
                    bfrag[j][1] = *reinterpret_cast<const uint32_t*>(bp + 16);
                }
                #pragma unroll
                for (int i = 0; i < 2; i++) {
                    const char* ap = As + (wm * 32 + i * 16 + fr) * (LDS_STRIDE * 2)
                                        + (kof + fc) * 2;
                    uint32_t a0 = *reinterpret_cast<const uint32_t*>(ap);
                    uint32_t a1 = *reinterpret_cast<const uint32_t*>(ap + 8 * LDS_STRIDE * 2);
                    uint32_t a2 = *reinterpret_cast<const uint32_t*>(ap + 16);
                    uint32_t a3 = *reinterpret_cast<const uint32_t*>(ap + 8 * LDS_STRIDE * 2 + 16);
                    #pragma unroll
                    for (int j = 0; j < 8; j++) {
                        asm volatile(
                            "mma.sync.aligned.m16n8k16.row.col.f32.bf16.bf16.f32 "
                            "{%0,%1,%2,%3}, {%4,%5,%6,%7}, {%8,%9}, {%0,%1,%2,%3};\n"
                            : "+f"(acc[i][j][0]), "+f"(acc[i][j][1]),
                              "+f"(acc[i][j][2]), "+f"(acc[i][j][3])
                            : "r"(a0), "r"(a1), "r"(a2), "r"(a3),
                              "r"(bfrag[j][0]), "r"(bfrag[j][1]));
                    }
                }
            }
            __syncwarp();
            if (lane == 0) mbar_arrive(sb + OFF_BAR + s * 16 + 8);
        }

        __syncthreads();   // producers' norm stores visible

        // ---- epilogue: dist = sqrt(max(xsq + csq - 2*cross, eps)) ----
        const float* xsq = (const float*)(smem + OFF_XSQ);
        const float* csq = (const float*)(smem + OFF_CSQ);
        #pragma unroll
        for (int i = 0; i < 2; i++) {
            const int row_l0 = wm * 32 + i * 16 + fr;
            #pragma unroll
            for (int hf = 0; hf < 2; hf++) {
                const int row_l = row_l0 + hf * 8;
                const float xq = xsq[row_l];
                float* orow = out + ((size_t)bm * BM + row_l) * KK + bn * BN;
                #pragma unroll
                for (int j = 0; j < 8; j++) {
                    const int col_l = wn * 64 + j * 8 + fc;
                    const float d0 = sqrtf(fmaxf(
                        xq + csq[col_l] - 2.f * acc[i][j][hf * 2 + 0], EPS_F));
                    const float d1 = sqrtf(fmaxf(
                        xq + csq[col_l + 1] - 2.f * acc[i][j][hf * 2 + 1], EPS_F));
                    *reinterpret_cast<float2*>(orow + col_l) = make_float2(d0, d1);
                }
            }
        }
        return;
    }
    __syncthreads();   // producers join the compute warps' pre-epilogue barrier
}

extern "C" void kernel_launch(void* const* d_in, const int* in_sizes, int n_in,
                              void* d_out, int out_size)
{
    const float* X = (const float*)d_in[0];   // inputs  [8192, 3072] fp32
    const float* C = (const float*)d_in[1];   // centers [256, 3072]  fp32
    float* out = (float*)d_out;               // [8192, 256] fp32

    cudaFuncSetAttribute(rbf_ws_kernel,
                         cudaFuncAttributeMaxDynamicSharedMemorySize, SMEM_BYTES);
    dim3 grid(KK / BN, BB / BM);              // (2, 64) = 128 CTAs
    rbf_ws_kernel<<<grid, NTHREADS, SMEM_BYTES>>>(X, C, out);
}

// round 5
// speedup vs baseline: 1.2435x; 1.2435x over previous
#include <cuda_runtime.h>
#include <cuda_bf16.h>
#include <cstdint>
#include <cstddef>

// Pairwise Euclidean distance, B=8192, K=256, D=3072, fp32.
// out[b,k] = sqrt(max(||x||^2 + ||c||^2 - 2 x.c, eps))
// sm_100 base ISA: bf16 mma.sync + ldmatrix, 4-stage SMEM ring,
// 2-deep LDG register staging, one __syncthreads per k-tile, no mbarriers.

#define BB 8192
#define KK 256
#define DD 3072
#define BM 128
#define BN 128
#define BK 32
#define NT (DD / BK)            // 96 k-tiles
#define NSTAGE 4
#define NTHREADS 256
#define EPS_F 1e-12f

#define ROW_B 80                 // bytes per tile row (32 bf16 + 8 pad) — ldmatrix conflict-free
#define ATILE_B (BM * ROW_B)     // 10240
#define STAGE_B (2 * ATILE_B)    // 20480 (A then B)
#define OFF_XSQ  (NSTAGE * STAGE_B)          // 81920
#define OFF_CSQ  (OFF_XSQ + 512)
#define SMEM_BYTES (OFF_CSQ + 512)           // 82944

static __device__ __forceinline__ uint32_t s2u(const void* p) {
    uint32_t a;
    asm("{.reg .u64 t; cvta.to.shared.u64 t, %1; cvt.u32.u64 %0, t;}"
        : "=r"(a) : "l"(p));
    return a;
}

#define LDSM_X4(r0, r1, r2, r3, a)                                            \
    asm volatile("ldmatrix.sync.aligned.m8n8.x4.shared.b16 {%0,%1,%2,%3}, [%4];" \
                 : "=r"(r0), "=r"(r1), "=r"(r2), "=r"(r3) : "r"(a))

__global__ void __launch_bounds__(NTHREADS, 1)
rbf_lm_kernel(const float* __restrict__ X, const float* __restrict__ C,
              float* __restrict__ out)
{
    extern __shared__ __align__(16) char smem[];
    const uint32_t sb = s2u(smem);
    const int tid  = threadIdx.x;
    const int wid  = tid >> 5;
    const int lane = tid & 31;
    const int bm = blockIdx.y;
    const int bn = blockIdx.x;

    if (tid < 128) {
        ((float*)(smem + OFF_XSQ))[tid] = 0.f;
        ((float*)(smem + OFF_CSQ))[tid] = 0.f;
    }

    // -------- producer mapping: thread t -> col4 = t&7, rows {32p + t>>3} --------
    const int lr = tid >> 3;     // 0..31
    const int c4 = tid & 7;      // float4 index within 32-float k-tile row
    const float4* gA = reinterpret_cast<const float4*>(X + (size_t)(bm * BM) * DD);
    const float4* gB = reinterpret_cast<const float4*>(C + (size_t)(bn * BN) * DD);
    const int row4 = DD / 4;     // 768

    float4 ra[2][4], rb[2][4];   // 2 staging buffers x 4 row-sheets
    float xs[4] = {0.f, 0.f, 0.f, 0.f};
    float cs[4] = {0.f, 0.f, 0.f, 0.f};

    auto ldg_tile = [&](int kt, int buf) {
        const int k4 = kt * (BK / 4);
        #pragma unroll
        for (int p = 0; p < 4; p++) {
            const int row = p * 32 + lr;
            ra[buf][p] = gA[(size_t)row * row4 + k4 + c4];
            rb[buf][p] = gB[(size_t)row * row4 + k4 + c4];
        }
    };

    auto sts_tile = [&](int kt, int buf) {
        const int s = kt & (NSTAGE - 1);
        const uint32_t base = sb + (uint32_t)s * STAGE_B;
        #pragma unroll
        for (int p = 0; p < 4; p++) {
            const int row = p * 32 + lr;
            const uint32_t off = (uint32_t)row * ROW_B + (uint32_t)c4 * 8;
            float4 v = ra[buf][p];
            xs[p] += v.x * v.x + v.y * v.y + v.z * v.z + v.w * v.w;
            __nv_bfloat162 q0 = __float22bfloat162_rn(make_float2(v.x, v.y));
            __nv_bfloat162 q1 = __float22bfloat162_rn(make_float2(v.z, v.w));
            asm volatile("st.shared.v2.b32 [%0], {%1,%2};"
                         :: "r"(base + off),
                            "r"(*reinterpret_cast<uint32_t*>(&q0)),
                            "r"(*reinterpret_cast<uint32_t*>(&q1)) : "memory");
            v = rb[buf][p];
            cs[p] += v.x * v.x + v.y * v.y + v.z * v.z + v.w * v.w;
            q0 = __float22bfloat162_rn(make_float2(v.x, v.y));
            q1 = __float22bfloat162_rn(make_float2(v.z, v.w));
            asm volatile("st.shared.v2.b32 [%0], {%1,%2};"
                         :: "r"(base + (uint32_t)ATILE_B + off),
                            "r"(*reinterpret_cast<uint32_t*>(&q0)),
                            "r"(*reinterpret_cast<uint32_t*>(&q1)) : "memory");
        }
    };

    // -------- compute mapping: 4x2 warp grid, warp tile 32(M) x 64(N) --------
    const int wm = wid & 3;
    const int wn = wid >> 2;
    const int fr = lane >> 2;
    const int fc = (lane & 3) * 2;
    // ldmatrix lane offset: g = lane>>3 selects (row-half, k-half)
    const int g  = lane >> 3;
    const int ri = lane & 7;
    const uint32_t lm_off = (uint32_t)(((g & 1) * 8 + ri) * ROW_B + (g >> 1) * 16);

    float acc[2][8][4];
    #pragma unroll
    for (int i = 0; i < 2; i++)
        #pragma unroll
        for (int j = 0; j < 8; j++)
            #pragma unroll
            for (int q = 0; q < 4; q++) acc[i][j][q] = 0.f;

    // -------- prologue: fill stages 0..2; ldg(k) lands in buf[(k+1)&1] --------
    ldg_tile(0, 1);
    ldg_tile(1, 0);
    sts_tile(0, 1);
    ldg_tile(2, 1);
    sts_tile(1, 0);
    ldg_tile(3, 0);
    sts_tile(2, 1);
    ldg_tile(4, 1);
    __syncthreads();

    // -------- mainloop: mma(kt); sts(kt+3); ldg(kt+5); sync --------
    #pragma unroll 1
    for (int kt = 0; kt < NT; kt++) {
        const uint32_t stA = sb + (uint32_t)(kt & (NSTAGE - 1)) * STAGE_B;
        const uint32_t stB = stA + ATILE_B;

        #pragma unroll
        for (int ks = 0; ks < 2; ks++) {
            const uint32_t kof = (uint32_t)ks * 32;   // 16 bf16 = 32B
            uint32_t a[2][4], b[4][4];
            #pragma unroll
            for (int im = 0; im < 2; im++) {
                const uint32_t ad = stA + (uint32_t)((wm * 32 + im * 16) * ROW_B)
                                        + kof + lm_off;
                LDSM_X4(a[im][0], a[im][1], a[im][2], a[im][3], ad);
            }
            #pragma unroll
            for (int jb = 0; jb < 4; jb++) {
                const uint32_t bd = stB + (uint32_t)((wn * 64 + jb * 16) * ROW_B)
                                        + kof + lm_off;
                LDSM_X4(b[jb][0], b[jb][1], b[jb][2], b[jb][3], bd);
            }
            #pragma unroll
            for (int im = 0; im < 2; im++)
                #pragma unroll
                for (int j = 0; j < 8; j++) {
                    const int jb = j >> 1, p = j & 1;
                    asm volatile(
                        "mma.sync.aligned.m16n8k16.row.col.f32.bf16.bf16.f32 "
                        "{%0,%1,%2,%3}, {%4,%5,%6,%7}, {%8,%9}, {%0,%1,%2,%3};\n"
                        : "+f"(acc[im][j][0]), "+f"(acc[im][j][1]),
                          "+f"(acc[im][j][2]), "+f"(acc[im][j][3])
                        : "r"(a[im][0]), "r"(a[im][1]), "r"(a[im][2]), "r"(a[im][3]),
                          "r"(b[jb][p]), "r"(b[jb][p + 2]));
                }
        }

        if (kt + 3 < NT) sts_tile(kt + 3, kt & 1);
        if (kt + 5 < NT) ldg_tile(kt + 5, kt & 1);
        __syncthreads();
    }

    // -------- norms: 8-way shared atomics, once per thread --------
    #pragma unroll
    for (int p = 0; p < 4; p++) {
        atomicAdd(&((float*)(smem + OFF_XSQ))[p * 32 + lr], xs[p]);
        atomicAdd(&((float*)(smem + OFF_CSQ))[p * 32 + lr], cs[p]);
    }
    __syncthreads();

    // -------- epilogue: dist = sqrt(max(xsq + csq - 2*cross, eps)) --------
    const float* xsq = (const float*)(smem + OFF_XSQ);
    const float* csq = (const float*)(smem + OFF_CSQ);
    #pragma unroll
    for (int i = 0; i < 2; i++) {
        const int row_l0 = wm * 32 + i * 16 + fr;
        #pragma unroll
        for (int hf = 0; hf < 2; hf++) {
            const int row_l = row_l0 + hf * 8;
            const float xq = xsq[row_l];
            float* orow = out + ((size_t)bm * BM + row_l) * KK + bn * BN;
            #pragma unroll
            for (int j = 0; j < 8; j++) {
                const int col_l = wn * 64 + j * 8 + fc;
                const float d0 = sqrtf(fmaxf(
                    xq + csq[col_l] - 2.f * acc[i][j][hf * 2 + 0], EPS_F));
                const float d1 = sqrtf(fmaxf(
                    xq + csq[col_l + 1] - 2.f * acc[i][j][hf * 2 + 1], EPS_F));
                *reinterpret_cast<float2*>(orow + col_l) = make_float2(d0, d1);
            }
        }
    }
}

extern "C" void kernel_launch(void* const* d_in, const int* in_sizes, int n_in,
                              void* d_out, int out_size)
{
    const float* X = (const float*)d_in[0];   // inputs  [8192, 3072] fp32
    const float* C = (const float*)d_in[1];   // centers [256, 3072]  fp32
    float* out = (float*)d_out;               // [8192, 256] fp32

    cudaFuncSetAttribute(rbf_lm_kernel,
                         cudaFuncAttributeMaxDynamicSharedMemorySize, SMEM_BYTES);
    dim3 grid(KK / BN, BB / BM);              // (2, 64) = 128 CTAs
    rbf_lm_kernel<<<grid, NTHREADS, SMEM_BYTES>>>(X, C, out);
}